// round 2
// baseline (speedup 1.0000x reference)
#include <cuda_runtime.h>
#include <cuda_bf16.h>
#include <cstdint>

// GIB_Layer: M=50000 queries, K=32 support, 4 kinds x G=8 gaussian basis fns,
// masked mean over K, then (32 x 16) mixing matmul. REACH=1, EPS=1e-8.
//
// R2: warp per query, lane k owns neighbor k. Ballot-compacted exp evaluation
// (mask density ~8%). Gather uses parity-aligned LDG.64+LDG.32 (2 loads, not
// 3). Epilogue is a pure-shuffle 32x16 dot (no shared memory at all): lane l
// accumulates output o=l&15 over features (l&16)+j via per-lane-src shfl,
// with the 16 lambda coefficients preloaded into registers.

#define GIB_K     32
#define GIB_OBS   16
#define GIB_F     32          // 4*G features
#define GIB_EPS   1e-8f
#define WPB       8           // warps per block
#define LOG2E     1.4426950408889634f

__device__ __forceinline__ float fast_exp2(float x) {
    float y;
    asm("ex2.approx.ftz.f32 %0, %1;" : "=f"(y) : "f"(x));
    return y;
}

__global__ __launch_bounds__(WPB * 32, 8)
void gib_layer_kernel(const float* __restrict__ points,
                      const float* __restrict__ q_coords,
                      const int*   __restrict__ support_idxs,
                      const float* __restrict__ cy_radius,
                      const float* __restrict__ disk_radius,
                      const float* __restrict__ disk_width,
                      const float* __restrict__ cone_radius,
                      const float* __restrict__ cone_inc,
                      const float* __restrict__ ellip_radii,
                      const float* __restrict__ lambdas,
                      float* __restrict__ out,
                      int M)
{
    const int lane = threadIdx.x & 31;
    const int wid  = threadIdx.x >> 5;
    const int m    = blockIdx.x * WPB + wid;

    // ---- per-lane weight coefficients: lane -> (kind = lane>>3, g = lane&7)
    // unified exponent (base 2): a*x2 + b*y2 + c*z2 + d*rz + k0,
    // where rz = sqrt(x2+y2+EPS)*z
    const int kind = lane >> 3;
    const int g    = lane & 7;
    float a, b, c, d, k0;
    {
        const float NHL = -0.5f * LOG2E;  // fold -1/2 and ln->log2 conversion
        if (kind == 0) {                  // cylinder: exp(-xy2 / (2 r^2))
            float r = cy_radius[g];
            float P = NHL / (r * r + GIB_EPS);
            a = P; b = P; c = 0.f; d = 0.f; k0 = 0.f;
        } else if (kind == 1) {           // cone: exp(-(rxy - z*inc)^2/(2 r^2))
            float r   = cone_radius[g];
            float inc = cone_inc[g];
            float Q = NHL / (r * r + GIB_EPS);
            // (rxy - z*inc)^2 = (xy2+EPS) - 2*rz*inc + z2*inc^2
            a = Q; b = Q; c = Q * inc * inc; d = -2.f * Q * inc; k0 = Q * GIB_EPS;
        } else if (kind == 2) {           // disk: exp(-0.5*(xy2/dr^2 + z2/dw^2))
            float dr = disk_radius[g], dw = disk_width[g];
            float Dr = NHL / (dr * dr + GIB_EPS);
            float Dw = NHL / (dw * dw + GIB_EPS);
            a = Dr; b = Dr; c = Dw; d = 0.f; k0 = 0.f;
        } else {                          // ellipsoid: per-axis radii
            float ra = ellip_radii[g * 3 + 0];
            float rb = ellip_radii[g * 3 + 1];
            float rc = ellip_radii[g * 3 + 2];
            a = NHL / (ra * ra + GIB_EPS);
            b = NHL / (rb * rb + GIB_EPS);
            c = NHL / (rc * rc + GIB_EPS);
            d = 0.f; k0 = 0.f;
        }
    }

    // ---- preload this lane's lambda column slice into registers.
    // lane l handles output o = l&15 over features f = (l&16) + j, j=0..15.
    const int o_idx = lane & 15;
    const int f0    = lane & 16;
    float lam[16];
    #pragma unroll
    for (int j = 0; j < 16; j++)
        lam[j] = lambdas[(f0 + j) * GIB_OBS + o_idx];

    if (m >= M) return;                   // whole warp exits together

    // ---- gather: lane k handles neighbor k.
    const float qx = q_coords[3 * m + 0];
    const float qy = q_coords[3 * m + 1];
    const float qz = q_coords[3 * m + 2];

    const int pi   = support_idxs[m * GIB_K + lane];
    const int odd  = pi & 1;
    // pi even: LDG.64 at 12*pi -> (x,y), scalar at +8 -> z
    // pi odd:  LDG.64 at 12*pi+4 -> (y,z), scalar at +0 -> x
    const float2 v2 = *reinterpret_cast<const float2*>(points + 3 * pi + odd);
    const float  vs = points[3 * pi + (odd ? 0 : 2)];

    const float x = (odd ? vs   : v2.x) - qx;
    const float y = (odd ? v2.x : v2.y) - qy;
    const float z = (odd ? v2.y : vs  ) - qz;

    const float x2 = x * x, y2 = y * y, z2 = z * z;
    const float d2 = x2 + y2 + z2;
    const float rz = sqrtf(x2 + y2 + GIB_EPS) * z;
    const bool  active = (d2 <= 1.0f);    // REACH^2 = 1

    unsigned bal = __ballot_sync(0xffffffffu, active);
    float acc = 0.f;
    while (bal) {
        const int j = __ffs(bal) - 1;
        bal &= bal - 1;
        const float bx2 = __shfl_sync(0xffffffffu, x2, j);
        const float by2 = __shfl_sync(0xffffffffu, y2, j);
        const float bz2 = __shfl_sync(0xffffffffu, z2, j);
        const float brz = __shfl_sync(0xffffffffu, rz, j);
        const float arg = fmaf(a, bx2, fmaf(b, by2, fmaf(c, bz2, fmaf(d, brz, k0))));
        acc += fast_exp2(arg);
    }
    acc *= (1.0f / (float)GIB_K);         // masked mean: sum(active w)/K

    // ---- epilogue: out[m, o] = sum_f feat[f] * lambdas[f, o], pure shuffle.
    // acc on lane f IS feature f. Half-warp split: lower half sums f=0..15,
    // upper half sums f=16..31 (for the same o), then combine across halves.
    float oacc = 0.f;
    #pragma unroll
    for (int j = 0; j < 16; j++) {
        const float bf = __shfl_sync(0xffffffffu, acc, f0 | j);
        oacc = fmaf(bf, lam[j], oacc);
    }
    oacc += __shfl_xor_sync(0xffffffffu, oacc, 16);

    if (lane < GIB_OBS)
        out[m * GIB_OBS + lane] = oacc;
}

extern "C" void kernel_launch(void* const* d_in, const int* in_sizes, int n_in,
                              void* d_out, int out_size)
{
    const float* points       = (const float*)d_in[0];
    const float* q_coords     = (const float*)d_in[1];
    const int*   support_idxs = (const int*)  d_in[2];
    const float* cy_radius    = (const float*)d_in[3];
    const float* disk_radius  = (const float*)d_in[4];
    const float* disk_width   = (const float*)d_in[5];
    const float* cone_radius  = (const float*)d_in[6];
    const float* cone_inc     = (const float*)d_in[7];
    const float* ellip_radii  = (const float*)d_in[8];
    const float* lambdas      = (const float*)d_in[9];
    float* out = (float*)d_out;

    const int M = in_sizes[1] / 3;        // q_coords is (M, 3)
    const int blocks = (M + WPB - 1) / WPB;

    gib_layer_kernel<<<blocks, WPB * 32>>>(points, q_coords, support_idxs,
                                           cy_radius, disk_radius, disk_width,
                                           cone_radius, cone_inc, ellip_radii,
                                           lambdas, out, M);
}

// round 3
// speedup vs baseline: 1.4864x; 1.4864x over previous
#include <cuda_runtime.h>
#include <cuda_bf16.h>
#include <cstdint>

// GIB_Layer: M=50000 queries, K=32 support, 4 kinds x G=8 gaussian basis fns,
// masked mean over K, then (32 x 16) mixing matmul. REACH=1, EPS=1e-8.
//
// R3: warp per query, lane k owns neighbor k. Ballot-compacted exp eval
// (mask density ~8%), unified per-lane coefficient form
//   w = 2^(a*x2 + b*y2 + c*z2 + d*rz + k0),  rz = sqrt(x2+y2+EPS)*z.
// Gather: parity-aligned LDG.64 + LDG.32 (2 loads/point, not 3).
// Epilogue: lambdas staged once per block into shared in a permuted layout
// (conflict-free LDS), features broadcast via register shfl, half-warp split
// over the 32 features, shfl_xor(16) combine. No per-query LDGs beyond the
// gather, no per-query shared traffic for features.

#define GIB_K     32
#define GIB_OBS   16
#define GIB_F     32          // 4*G features
#define GIB_EPS   1e-8f
#define WPB       8           // warps per block
#define LOG2E     1.4426950408889634f

__device__ __forceinline__ float fast_exp2(float x) {
    float y;
    asm("ex2.approx.ftz.f32 %0, %1;" : "=f"(y) : "f"(x));
    return y;
}

__global__ __launch_bounds__(WPB * 32, 8)
void gib_layer_kernel(const float* __restrict__ points,
                      const float* __restrict__ q_coords,
                      const int*   __restrict__ support_idxs,
                      const float* __restrict__ cy_radius,
                      const float* __restrict__ disk_radius,
                      const float* __restrict__ disk_width,
                      const float* __restrict__ cone_radius,
                      const float* __restrict__ cone_inc,
                      const float* __restrict__ ellip_radii,
                      const float* __restrict__ lambdas,
                      float* __restrict__ out,
                      int M)
{
    // Permuted lambda staging: s_lam2[j][l] = lambdas[((l&16)+j)*OBS + (l&15)]
    // so in the epilogue, iteration j reads 32 consecutive words (1 wavefront).
    __shared__ float s_lam2[16][32];
    for (int i = threadIdx.x; i < GIB_F * GIB_OBS; i += blockDim.x) {
        const int j = i >> 5, l = i & 31;
        s_lam2[j][l] = lambdas[((l & 16) + j) * GIB_OBS + (l & 15)];
    }

    const int lane = threadIdx.x & 31;
    const int wid  = threadIdx.x >> 5;
    const int m    = blockIdx.x * WPB + wid;

    // ---- per-lane weight coefficients: lane -> (kind = lane>>3, g = lane&7)
    const int kind = lane >> 3;
    const int g    = lane & 7;
    float a, b, c, d, k0;
    {
        const float NHL = -0.5f * LOG2E;  // fold -1/2 and ln->log2 conversion
        if (kind == 0) {                  // cylinder: exp(-xy2 / (2 r^2))
            float r = cy_radius[g];
            float P = NHL / (r * r + GIB_EPS);
            a = P; b = P; c = 0.f; d = 0.f; k0 = 0.f;
        } else if (kind == 1) {           // cone: exp(-(rxy - z*inc)^2/(2 r^2))
            float r   = cone_radius[g];
            float inc = cone_inc[g];
            float Q = NHL / (r * r + GIB_EPS);
            // (rxy - z*inc)^2 = (xy2+EPS) - 2*rz*inc + z2*inc^2
            a = Q; b = Q; c = Q * inc * inc; d = -2.f * Q * inc; k0 = Q * GIB_EPS;
        } else if (kind == 2) {           // disk: exp(-0.5*(xy2/dr^2 + z2/dw^2))
            float dr = disk_radius[g], dw = disk_width[g];
            float Dr = NHL / (dr * dr + GIB_EPS);
            float Dw = NHL / (dw * dw + GIB_EPS);
            a = Dr; b = Dr; c = Dw; d = 0.f; k0 = 0.f;
        } else {                          // ellipsoid: per-axis radii
            float ra = ellip_radii[g * 3 + 0];
            float rb = ellip_radii[g * 3 + 1];
            float rc = ellip_radii[g * 3 + 2];
            a = NHL / (ra * ra + GIB_EPS);
            b = NHL / (rb * rb + GIB_EPS);
            c = NHL / (rc * rc + GIB_EPS);
            d = 0.f; k0 = 0.f;
        }
    }

    __syncthreads();                      // s_lam2 ready
    if (m >= M) return;                   // whole warp exits together

    // ---- gather: lane k handles neighbor k (parity-aligned vector load)
    const float qx = q_coords[3 * m + 0];
    const float qy = q_coords[3 * m + 1];
    const float qz = q_coords[3 * m + 2];

    const int pi   = support_idxs[m * GIB_K + lane];
    const int odd  = pi & 1;
    // pi even: LDG.64 at 12*pi -> (x,y), scalar at +8 -> z
    // pi odd:  LDG.64 at 12*pi+4 -> (y,z), scalar at +0 -> x
    const float2 v2 = *reinterpret_cast<const float2*>(points + 3 * pi + odd);
    const float  vs = points[3 * pi + (odd ? 0 : 2)];

    const float x = (odd ? vs   : v2.x) - qx;
    const float y = (odd ? v2.x : v2.y) - qy;
    const float z = (odd ? v2.y : vs  ) - qz;

    const float x2 = x * x, y2 = y * y, z2 = z * z;
    const float d2 = x2 + y2 + z2;
    const float rz = sqrtf(x2 + y2 + GIB_EPS) * z;
    const bool  active = (d2 <= 1.0f);    // REACH^2 = 1

    unsigned bal = __ballot_sync(0xffffffffu, active);
    float acc = 0.f;
    while (bal) {
        const int j = __ffs(bal) - 1;
        bal &= bal - 1;
        const float bx2 = __shfl_sync(0xffffffffu, x2, j);
        const float by2 = __shfl_sync(0xffffffffu, y2, j);
        const float bz2 = __shfl_sync(0xffffffffu, z2, j);
        const float brz = __shfl_sync(0xffffffffu, rz, j);
        const float arg = fmaf(a, bx2, fmaf(b, by2, fmaf(c, bz2, fmaf(d, brz, k0))));
        acc += fast_exp2(arg);
    }
    acc *= (1.0f / (float)GIB_K);         // masked mean: sum(active w)/K

    // ---- epilogue: out[m, o] = sum_f feat[f] * lambdas[f, o].
    // acc on lane f IS feature f. Lane l accumulates output o=l&15 over
    // features (l&16)+j; lambda comes from conflict-free shared row.
    const int f0 = lane & 16;
    float oacc = 0.f;
    #pragma unroll
    for (int j = 0; j < 16; j++) {
        const float bf = __shfl_sync(0xffffffffu, acc, f0 | j);
        oacc = fmaf(bf, s_lam2[j][lane], oacc);
    }
    oacc += __shfl_xor_sync(0xffffffffu, oacc, 16);

    if (lane < GIB_OBS)
        out[m * GIB_OBS + lane] = oacc;
}

extern "C" void kernel_launch(void* const* d_in, const int* in_sizes, int n_in,
                              void* d_out, int out_size)
{
    const float* points       = (const float*)d_in[0];
    const float* q_coords     = (const float*)d_in[1];
    const int*   support_idxs = (const int*)  d_in[2];
    const float* cy_radius    = (const float*)d_in[3];
    const float* disk_radius  = (const float*)d_in[4];
    const float* disk_width   = (const float*)d_in[5];
    const float* cone_radius  = (const float*)d_in[6];
    const float* cone_inc     = (const float*)d_in[7];
    const float* ellip_radii  = (const float*)d_in[8];
    const float* lambdas      = (const float*)d_in[9];
    float* out = (float*)d_out;

    const int M = in_sizes[1] / 3;        // q_coords is (M, 3)
    const int blocks = (M + WPB - 1) / WPB;

    gib_layer_kernel<<<blocks, WPB * 32>>>(points, q_coords, support_idxs,
                                           cy_radius, disk_radius, disk_width,
                                           cone_radius, cone_inc, ellip_radii,
                                           lambdas, out, M);
}

// round 4
// speedup vs baseline: 1.9797x; 1.3319x over previous
#include <cuda_runtime.h>
#include <cuda_bf16.h>
#include <cstdint>

// GIB_Layer: M=50000 queries, K=32 support, 4 kinds x G=8 gaussian basis fns,
// masked mean over K, then (32 x 16) mixing matmul. REACH=1, EPS=1e-8.
//
// R4: grid-stride multi-query warps (~8 queries/warp). All query-invariant
// setup hoisted out of the query loop:
//   - per-lane unified coefficients (a,b,c,d,k0), incl. the divisions
//   - 16-register lambda slice per lane (lane l: outputs o=l&15 over
//     features f=(l&16)+j)
// Per query: parity-aligned LDG.64+LDG.32 gather, ballot-compacted exp
// (mask density ~8%), pure-shuffle 32x16 epilogue vs. register lambdas.
// No shared memory, no __syncthreads.

#define GIB_K     32
#define GIB_OBS   16
#define GIB_F     32          // 4*G features
#define GIB_EPS   1e-8f
#define WPB       4           // warps per block
#define QPW       8           // target queries per warp
#define LOG2E     1.4426950408889634f

__device__ __forceinline__ float fast_exp2(float x) {
    float y;
    asm("ex2.approx.ftz.f32 %0, %1;" : "=f"(y) : "f"(x));
    return y;
}

__global__ __launch_bounds__(WPB * 32)
void gib_layer_kernel(const float* __restrict__ points,
                      const float* __restrict__ q_coords,
                      const int*   __restrict__ support_idxs,
                      const float* __restrict__ cy_radius,
                      const float* __restrict__ disk_radius,
                      const float* __restrict__ disk_width,
                      const float* __restrict__ cone_radius,
                      const float* __restrict__ cone_inc,
                      const float* __restrict__ ellip_radii,
                      const float* __restrict__ lambdas,
                      float* __restrict__ out,
                      int M)
{
    const int lane      = threadIdx.x & 31;
    const int warp_glb  = (blockIdx.x * WPB) + (threadIdx.x >> 5);
    const int num_warps = gridDim.x * WPB;

    // ---- per-lane weight coefficients (query-invariant, once per warp):
    // lane -> (kind = lane>>3, g = lane&7); unified base-2 exponent
    //   a*x2 + b*y2 + c*z2 + d*rz + k0,  rz = sqrt(x2+y2+EPS)*z
    const int kind = lane >> 3;
    const int g    = lane & 7;
    float a, b, c, d, k0;
    {
        const float NHL = -0.5f * LOG2E;
        if (kind == 0) {                  // cylinder: exp(-xy2 / (2 r^2))
            float r = cy_radius[g];
            float P = NHL / (r * r + GIB_EPS);
            a = P; b = P; c = 0.f; d = 0.f; k0 = 0.f;
        } else if (kind == 1) {           // cone: exp(-(rxy - z*inc)^2/(2 r^2))
            float r   = cone_radius[g];
            float inc = cone_inc[g];
            float Q = NHL / (r * r + GIB_EPS);
            a = Q; b = Q; c = Q * inc * inc; d = -2.f * Q * inc; k0 = Q * GIB_EPS;
        } else if (kind == 2) {           // disk: exp(-0.5*(xy2/dr^2+z2/dw^2))
            float dr = disk_radius[g], dw = disk_width[g];
            float Dr = NHL / (dr * dr + GIB_EPS);
            float Dw = NHL / (dw * dw + GIB_EPS);
            a = Dr; b = Dr; c = Dw; d = 0.f; k0 = 0.f;
        } else {                          // ellipsoid: per-axis radii
            float ra = ellip_radii[g * 3 + 0];
            float rb = ellip_radii[g * 3 + 1];
            float rc = ellip_radii[g * 3 + 2];
            a = NHL / (ra * ra + GIB_EPS);
            b = NHL / (rb * rb + GIB_EPS);
            c = NHL / (rc * rc + GIB_EPS);
            d = 0.f; k0 = 0.f;
        }
    }

    // ---- per-lane lambda slice (query-invariant, once per warp):
    // lane l handles output o=l&15 over features f=(l&16)+j, j=0..15.
    const int o_idx = lane & 15;
    const int f0    = lane & 16;
    float lam[16];
    #pragma unroll
    for (int j = 0; j < 16; j++)
        lam[j] = lambdas[(f0 + j) * GIB_OBS + o_idx];

    // ---- query loop (grid-stride): whole warp shares one m per iteration.
    for (int m = warp_glb; m < M; m += num_warps) {
        const float qx = q_coords[3 * m + 0];
        const float qy = q_coords[3 * m + 1];
        const float qz = q_coords[3 * m + 2];

        const int pi  = support_idxs[m * GIB_K + lane];
        const int odd = pi & 1;
        // pi even: LDG.64 at 12*pi -> (x,y), scalar +8 -> z
        // pi odd:  LDG.64 at 12*pi+4 -> (y,z), scalar +0 -> x
        const float2 v2 = *reinterpret_cast<const float2*>(points + 3 * pi + odd);
        const float  vs = points[3 * pi + (odd ? 0 : 2)];

        const float x = (odd ? vs   : v2.x) - qx;
        const float y = (odd ? v2.x : v2.y) - qy;
        const float z = (odd ? v2.y : vs  ) - qz;

        const float x2 = x * x, y2 = y * y, z2 = z * z;
        const float d2 = x2 + y2 + z2;
        const float rz = sqrtf(x2 + y2 + GIB_EPS) * z;
        const bool  active = (d2 <= 1.0f);    // REACH^2 = 1

        unsigned bal = __ballot_sync(0xffffffffu, active);
        float acc = 0.f;
        while (bal) {
            const int j = __ffs(bal) - 1;
            bal &= bal - 1;
            const float bx2 = __shfl_sync(0xffffffffu, x2, j);
            const float by2 = __shfl_sync(0xffffffffu, y2, j);
            const float bz2 = __shfl_sync(0xffffffffu, z2, j);
            const float brz = __shfl_sync(0xffffffffu, rz, j);
            const float arg = fmaf(a, bx2, fmaf(b, by2, fmaf(c, bz2, fmaf(d, brz, k0))));
            acc += fast_exp2(arg);
        }
        acc *= (1.0f / (float)GIB_K);     // masked mean: sum(active w)/K

        // ---- epilogue: out[m, o] = sum_f feat[f] * lambdas[f, o].
        // acc on lane f IS feature f; half-warp split over features.
        float oacc = 0.f;
        #pragma unroll
        for (int j = 0; j < 16; j++) {
            const float bf = __shfl_sync(0xffffffffu, acc, f0 | j);
            oacc = fmaf(bf, lam[j], oacc);
        }
        oacc += __shfl_xor_sync(0xffffffffu, oacc, 16);

        if (lane < GIB_OBS)
            out[m * GIB_OBS + lane] = oacc;
    }
}

extern "C" void kernel_launch(void* const* d_in, const int* in_sizes, int n_in,
                              void* d_out, int out_size)
{
    const float* points       = (const float*)d_in[0];
    const float* q_coords     = (const float*)d_in[1];
    const int*   support_idxs = (const int*)  d_in[2];
    const float* cy_radius    = (const float*)d_in[3];
    const float* disk_radius  = (const float*)d_in[4];
    const float* disk_width   = (const float*)d_in[5];
    const float* cone_radius  = (const float*)d_in[6];
    const float* cone_inc     = (const float*)d_in[7];
    const float* ellip_radii  = (const float*)d_in[8];
    const float* lambdas      = (const float*)d_in[9];
    float* out = (float*)d_out;

    const int M = in_sizes[1] / 3;        // q_coords is (M, 3)
    // ~QPW queries per warp
    int blocks = (M + WPB * 32 * 0 + (WPB * QPW) - 1) / (WPB * QPW);
    if (blocks < 1) blocks = 1;

    gib_layer_kernel<<<blocks, WPB * 32>>>(points, q_coords, support_idxs,
                                           cy_radius, disk_radius, disk_width,
                                           cone_radius, cone_inc, ellip_radii,
                                           lambdas, out, M);
}